// round 15
// baseline (speedup 1.0000x reference)
#include <cuda_runtime.h>

#define B_TOT   16
#define CIN     64
#define COUT    64
#define S_LEN   1024
#define KW      3
#define STILE   32
#define POSN    34                     // 32 + 2 halo positions
#define XSLOT   9                      // 8 b-slots + 1 pad word (bank bijection)
#define XCROW   (POSN * XSLOT)         // 306 words per c
#define BH      8
#define OTILE   4
#define OBLK    32                     // o per block
#define CHALF   32                     // c per warp-half
#define NTHREADS 512                   // 16 warps: [ch 2][og 8]
#define SK      (S_LEN * KW)           // per-c weight stride (floats) = 3072
#define OCS     (CIN * S_LEN * KW)     // per-o weight stride (floats)
#define WSLICE  384                    // bytes per (o,c,s-tile) weight slice
#define WWARP   (OTILE * WSLICE)       // 1536 B staged per warp per c-iter
#define XTILE_WORDS (CIN * XCROW)      // 19584 words
#define XTILE_BYTES (XTILE_WORDS * 4)  // 78336 B
#define WSM_BYTES   (16 * 2 * WWARP)   // 49152 B (16 warps x 2 stages)
#define SMEM_BYTES  (XTILE_BYTES + WSM_BYTES)  // 127488 B

#define CPA16(dst_u32, src_ptr) \
    asm volatile("cp.async.cg.shared.global [%0], [%1], 16;" \
                 :: "r"(dst_u32), "l"(src_ptr))

__global__ void __launch_bounds__(NTHREADS)
locon1d_kernel(const float* __restrict__ X,     // (B, Cin, S)
               const float* __restrict__ W,     // (Cout, Cin, S, K)
               const float* __restrict__ Bias,  // (Cout, S)
               float* __restrict__ Out)         // (B, Cout, S)
{
    extern __shared__ float smem[];
    float* xt  = smem;                                   // x tile
    char*  wsm = (char*)(smem + XTILE_WORDS);            // staged weights

    const int s0     = blockIdx.x * STILE;
    const int o0base = blockIdx.y * OBLK;
    const int b0     = blockIdx.z * BH;
    const int tid    = threadIdx.x;
    const int sl     = tid & 31;
    const int wid    = tid >> 5;          // 0..15
    const int og     = wid & 7;
    const int ch     = wid >> 3;          // c-half
    const int sq     = sl & 7;            // s-quad id: thread covers s0+4sq..+3
    const int bg     = sl >> 3;           // b-group: thread covers b0+2bg, +1

    // ── x tile fill: warp -> (batch bf, c-half chf). Layout [c][pos][slot],
    //    slot = sigma(b) = 4*(b&1) + (b>>1)  (makes mainloop LDS banks bijective).
    {
        const int  bf   = wid >> 1;
        const int  chf  = wid & 1;
        const int  slot = 4 * (bf & 1) + (bf >> 1);
        const float* xb = X + ((size_t)(b0 + bf) * CIN + chf * CHALF) * S_LEN;
        float*      shb = xt + (size_t)(chf * CHALF) * XCROW + slot;
        const int  sg  = s0 - 1 + sl;
        const bool m1  = (unsigned)sg < (unsigned)S_LEN;
        const int  sg2 = s0 + 31 + sl;
        const bool m2  = (sl < 2) && ((unsigned)sg2 < (unsigned)S_LEN);
        #pragma unroll 4
        for (int c = 0; c < CHALF; c++) {
            shb[(size_t)c * XCROW + sl * XSLOT] =
                m1 ? xb[(size_t)c * S_LEN + sg] : 0.0f;
            if (sl < 2)
                shb[(size_t)c * XCROW + (32 + sl) * XSLOT] =
                    m2 ? xb[(size_t)c * S_LEN + sg2] : 0.0f;
        }
    }
    __syncthreads();

    const int o0     = o0base + og * OTILE;
    const int chbase = ch * CHALF;

    // acc[j][i][t]: 4 o x 4 s x 2 b = 32 regs. ch0 seeds bias, ch1 zero.
    float acc[OTILE][4][2];
    #pragma unroll
    for (int j = 0; j < OTILE; j++) {
        float4 bv = make_float4(0.f, 0.f, 0.f, 0.f);
        if (ch == 0)
            bv = *(const float4*)(Bias + (size_t)(o0 + j) * S_LEN + s0 + 4 * sq);
        #pragma unroll
        for (int t = 0; t < 2; t++) {
            acc[j][0][t] = bv.x; acc[j][1][t] = bv.y;
            acc[j][2][t] = bv.z; acc[j][3][t] = bv.w;
        }
    }

    // ── cp.async staging setup: warp stages its 4 (o,c) slices (1536 B) per
    //    c-iter as 3x 32-lane 16B copies. Per-lane chunk mapping precomputed.
    const char* wg0 = (const char*)(W + (size_t)o0 * OCS
                                      + (size_t)chbase * SK
                                      + (size_t)s0 * KW);
    unsigned goff[3];
    #pragma unroll
    for (int m = 0; m < 3; m++) {
        int g   = m * 32 + sl;          // global chunk id 0..95
        int jm  = g / 24;               // which o-slice
        int off = g - jm * 24;          // 16B chunk within slice
        goff[m] = (unsigned)(jm * (OCS * 4) + off * 16);
    }
    const unsigned wsw = (unsigned)__cvta_generic_to_shared(wsm + wid * (2 * WWARP));

    // preload stage 0 (ci = 0)
    #pragma unroll
    for (int m = 0; m < 3; m++)
        CPA16(wsw + (unsigned)((m * 32 + sl) * 16), wg0 + goff[m]);
    asm volatile("cp.async.commit_group;" ::: "memory");

    const float* xrd = xt + (size_t)chbase * XCROW + 36 * sq + bg;
    const float4* wrd = (const float4*)(wsm + wid * (2 * WWARP)) + sq * 3;

    #pragma unroll 2
    for (int ci = 0; ci < CHALF; ci++) {
        const int stg = ci & 1;
        if (ci + 1 < CHALF) {
            const char* src = wg0 + (size_t)(ci + 1) * (SK * 4);
            const unsigned dst = wsw + (unsigned)((stg ^ 1) * WWARP);
            #pragma unroll
            for (int m = 0; m < 3; m++)
                CPA16(dst + (unsigned)((m * 32 + sl) * 16), src + goff[m]);
            asm volatile("cp.async.commit_group;" ::: "memory");
            asm volatile("cp.async.wait_group 1;" ::: "memory");
        } else {
            asm volatile("cp.async.wait_group 0;" ::: "memory");
        }
        __syncwarp();

        // x window: 6 taps x 2 b, all 1-pass LDS (banks 4sq+bg bijective).
        float xv[2][6];
        const float* xr = xrd + (size_t)ci * XCROW;
        #pragma unroll
        for (int t = 0; t < 2; t++)
            #pragma unroll
            for (int d = 0; d < 6; d++)
                xv[t][d] = xr[d * XSLOT + 4 * t];

        // weights from smem: 3 LDS.128 per o, 1-pass (banks 12sq+qk tile 32).
        const float4* wq = wrd + stg * (WWARP / 16);
        #pragma unroll
        for (int j = 0; j < OTILE; j++) {
            const float4 q0 = wq[j * 24 + 0];
            const float4 q1 = wq[j * 24 + 1];
            const float4 q2 = wq[j * 24 + 2];
            #pragma unroll
            for (int t = 0; t < 2; t++) {
                acc[j][0][t] += q0.x * xv[t][0];
                acc[j][0][t] += q0.y * xv[t][1];
                acc[j][0][t] += q0.z * xv[t][2];
                acc[j][1][t] += q0.w * xv[t][1];
                acc[j][1][t] += q1.x * xv[t][2];
                acc[j][1][t] += q1.y * xv[t][3];
                acc[j][2][t] += q1.z * xv[t][2];
                acc[j][2][t] += q1.w * xv[t][3];
                acc[j][2][t] += q2.x * xv[t][4];
                acc[j][3][t] += q2.y * xv[t][3];
                acc[j][3][t] += q2.z * xv[t][4];
                acc[j][3][t] += q2.w * xv[t][5];
            }
        }
    }

    // ── Cross-half reduction (reuse x tile; constant acc indexing only).
    __syncthreads();
    float* rbuf = xt;                       // 32 x 256 floats = 32 KB < x tile
    const int t2 = og * 32 + sl;
    if (ch == 1) {
        #pragma unroll
        for (int j = 0; j < OTILE; j++)
            #pragma unroll
            for (int i = 0; i < 4; i++)
                #pragma unroll
                for (int t = 0; t < 2; t++)
                    rbuf[((j * 4 + i) * 2 + t) * 256 + t2] = acc[j][i][t];
    }
    __syncthreads();
    if (ch == 0) {
        #pragma unroll
        for (int j = 0; j < OTILE; j++) {
            #pragma unroll
            for (int t = 0; t < 2; t++) {
                float4 v;
                v.x = acc[j][0][t] + rbuf[((j * 4 + 0) * 2 + t) * 256 + t2];
                v.y = acc[j][1][t] + rbuf[((j * 4 + 1) * 2 + t) * 256 + t2];
                v.z = acc[j][2][t] + rbuf[((j * 4 + 2) * 2 + t) * 256 + t2];
                v.w = acc[j][3][t] + rbuf[((j * 4 + 3) * 2 + t) * 256 + t2];
                // 4 consecutive s -> one STG.128, 16B-aligned (s0+4sq).
                *(float4*)(Out + ((size_t)(b0 + 2 * bg + t) * COUT + (o0 + j)) * S_LEN
                               + s0 + 4 * sq) = v;
            }
        }
    }
}

extern "C" void kernel_launch(void* const* d_in, const int* in_sizes, int n_in,
                              void* d_out, int out_size) {
    const float* x    = (const float*)d_in[0];
    const float* w    = (const float*)d_in[1];
    const float* bias = (const float*)d_in[2];
    float* out        = (float*)d_out;

    cudaFuncSetAttribute(locon1d_kernel,
                         cudaFuncAttributeMaxDynamicSharedMemorySize, SMEM_BYTES);

    dim3 grid(S_LEN / STILE, COUT / OBLK, B_TOT / BH);  // (32, 2, 2) = 128 blocks
    locon1d_kernel<<<grid, NTHREADS, SMEM_BYTES>>>(x, w, bias, out);
}

// round 16
// speedup vs baseline: 1.4973x; 1.4973x over previous
#include <cuda_runtime.h>

#define B_TOT   16
#define CIN     64
#define COUT    64
#define S_LEN   1024
#define KW      3
#define STILE   32
#define POSN    (STILE + 2)     // 34 input positions per tile (halo of 1 each side)
#define BH      8               // batches per block
#define OTILE   4               // outputs per thread
#define OGN     8               // o-groups per c-half
#define OBLK    (OGN * OTILE)   // 32 outputs per block
#define CHALF   (CIN / 2)       // 32 c per warp-half
#define NTHREADS 512            // 16 warps: [c-half][o-group]
#define SMEM_FLOATS (CIN * BH * POSN)   // 64*8*34 = 17408 floats = 69632 B

__global__ void __launch_bounds__(NTHREADS)
locon1d_kernel(const float* __restrict__ X,     // (B, Cin, S)
               const float* __restrict__ W,     // (Cout, Cin, S, K)
               const float* __restrict__ Bias,  // (Cout, S)
               float* __restrict__ Out)         // (B, Cout, S)
{
    extern __shared__ float shx[];   // [c][b][pos] -> (c*BH + b)*POSN + pos

    const int s0     = blockIdx.x * STILE;
    const int o0base = blockIdx.y * OBLK;
    const int b0     = blockIdx.z * BH;
    const int tid    = threadIdx.x;

    // ── Cooperative input tile fill (512 threads, coalesced along pos).
    for (int i = tid; i < SMEM_FLOATS; i += NTHREADS) {
        int pos = i % POSN;
        int bc  = i / POSN;
        int b   = bc % BH;
        int c   = bc / BH;
        int sg  = s0 - 1 + pos;
        float v = 0.0f;
        if ((unsigned)sg < (unsigned)S_LEN)
            v = X[((size_t)(b0 + b) * CIN + c) * S_LEN + sg];
        shx[i] = v;
    }
    __syncthreads();

    const int sl = tid & 31;          // lane = consecutive s
    const int wid = tid >> 5;         // 0..15
    const int og  = wid & 7;          // o-group
    const int ch  = wid >> 3;         // c-half: 0 or 1

    const int s  = s0 + sl;
    const int o0 = o0base + og * OTILE;

    // acc[j][b]: 4 outputs x 8 batches = 32 registers.
    // c-half 0 starts from bias; c-half 1 starts from zero (partial sum).
    float acc[OTILE][BH];
    #pragma unroll
    for (int j = 0; j < OTILE; j++) {
        float bv = (ch == 0) ? Bias[(size_t)(o0 + j) * S_LEN + s] : 0.0f;
        #pragma unroll
        for (int b = 0; b < BH; b++) acc[j][b] = bv;
    }

    // Weight base for (o0, c = ch*CHALF, s, k=0).
    const float* wbase = W + (size_t)o0 * (CIN * S_LEN * KW)
                           + (size_t)(ch * CHALF) * (S_LEN * KW)
                           + (size_t)s * KW;
    const float* xhalf = shx + (size_t)(ch * CHALF) * (BH * POSN) + sl;

    // Single change vs the 23.0us kernel: unroll 2 -> 4. 128-reg budget
    // (512 thr x 128 = full RF, occupancy unchanged) lets ptxas batch ~4
    // iterations of weight LDGs instead of ~2.
    #pragma unroll 4
    for (int ci = 0; ci < CHALF; ci++) {
        // x window: 8 batches x 3 taps from shared (conflict-free: lanes are the
        // fastest smem dimension).
        float xr[BH][KW];
        const float* xc = xhalf + (size_t)ci * (BH * POSN);
        #pragma unroll
        for (int b = 0; b < BH; b++) {
            #pragma unroll
            for (int k = 0; k < KW; k++)
                xr[b][k] = xc[b * POSN + k];
        }

        const float* wc = wbase + (size_t)ci * (S_LEN * KW);
        #pragma unroll
        for (int j = 0; j < OTILE; j++) {
            const float* wj = wc + (size_t)j * (CIN * S_LEN * KW);
            float w0 = wj[0];
            float w1 = wj[1];
            float w2 = wj[2];
            #pragma unroll
            for (int b = 0; b < BH; b++) {
                acc[j][b] += w0 * xr[b][0];
                acc[j][b] += w1 * xr[b][1];
                acc[j][b] += w2 * xr[b][2];
            }
        }
    }

    // ── Cross-half reduction through smem (reuse shx; x tile is dead now).
    //    Compile-time-constant acc indexing ONLY (dynamic indexing spills).
    __syncthreads();                       // all mainloop reads of shx done
    const int t2 = og * 32 + sl;           // 0..255 thread id within a half
    if (ch == 1) {
        #pragma unroll
        for (int j = 0; j < OTILE; j++)
            #pragma unroll
            for (int b = 0; b < BH; b++)
                shx[(j * BH + b) * 256 + t2] = acc[j][b];
    }
    __syncthreads();
    if (ch == 0) {
        #pragma unroll
        for (int j = 0; j < OTILE; j++) {
            #pragma unroll
            for (int b = 0; b < BH; b++) {
                float v = acc[j][b] + shx[(j * BH + b) * 256 + t2];
                // lanes = consecutive s -> fully coalesced 128B stores per warp.
                Out[((size_t)(b0 + b) * COUT + (o0 + j)) * S_LEN + s] = v;
            }
        }
    }
}

extern "C" void kernel_launch(void* const* d_in, const int* in_sizes, int n_in,
                              void* d_out, int out_size) {
    const float* x    = (const float*)d_in[0];
    const float* w    = (const float*)d_in[1];
    const float* bias = (const float*)d_in[2];
    float* out        = (float*)d_out;

    const int smem_bytes = SMEM_FLOATS * (int)sizeof(float);  // 69632 B > 48K -> opt-in
    cudaFuncSetAttribute(locon1d_kernel,
                         cudaFuncAttributeMaxDynamicSharedMemorySize, smem_bytes);

    dim3 grid(S_LEN / STILE, COUT / OBLK, B_TOT / BH);  // (32, 2, 2) = 128 blocks
    locon1d_kernel<<<grid, NTHREADS, smem_bytes>>>(x, w, bias, out);
}